// round 3
// baseline (speedup 1.0000x reference)
#include <cuda_runtime.h>
#include <cstdint>

#define C_DIM 64
#define F_DIM 128
#define DEG 32
#define MAX_N 20000
#define MAX_E 640000
#define WARPS_PER_CTA 8
#define CNT_STRIDE 68    // words per s_cnt row

// Scratch (device globals: no allocations allowed in kernel_launch)
__device__ float g_wt[F_DIM * C_DIM];   // permuted W^T [f][perm(c)], tf32 (L1-resident)
__device__ int   g_cursor[MAX_N];
__device__ int   g_edge[MAX_E];         // per-node edge lists, DEG per node

// involutive column permutation within 16-col groups: l = a+4b -> 4a+b.
// Makes (kc, kc+4) pairs of k-steps 2d,2d+1 one contiguous float4 at d*16+4*tig.
__device__ __forceinline__ int perm64(int c) {
    int l = c & 15;
    return (c & ~15) | (4 * (l & 3) + (l >> 2));
}

// ---------------------------------------------------------------------------
// prep1: zero cursors (all blocks) + softmax W^T permuted tf32 (last block)
// ---------------------------------------------------------------------------
__global__ void prep1_kernel(const float* __restrict__ imp, int n_nodes) {
    if (blockIdx.x == gridDim.x - 1) {
        int f = threadIdx.x;
        if (f < F_DIM) {
            float v[C_DIM];
            float m = -3.0e38f;
#pragma unroll
            for (int c = 0; c < C_DIM; c++) { v[c] = imp[c * F_DIM + f]; m = fmaxf(m, v[c]); }
            float s = 0.f;
#pragma unroll
            for (int c = 0; c < C_DIM; c++) { v[c] = expf(v[c] - m); s += v[c]; }
            float inv = 1.0f / s;
#pragma unroll
            for (int c = 0; c < C_DIM; c++) {
                float w = v[c] * inv;
                uint32_t t;
                asm("cvt.rna.tf32.f32 %0, %1;" : "=r"(t) : "f"(w));
                g_wt[f * C_DIM + perm64(c)] = __uint_as_float(t);
            }
        }
    } else {
        int i = blockIdx.x * blockDim.x + threadIdx.x;
        if (i < n_nodes) g_cursor[i] = 0;
    }
}

__global__ void scatter_kernel(const int* __restrict__ dst, int n_edges) {
    int e = blockIdx.x * blockDim.x + threadIdx.x;
    if (e < n_edges) {
        int d = dst[e];
        int slot = atomicAdd(&g_cursor[d], 1);
        if (slot < DEG) g_edge[d * DEG + slot] = e;
    }
}

// ---------------------------------------------------------------------------
// Main fused kernel: one warp = one node. No CTA-level sync at all.
// ---------------------------------------------------------------------------
__global__ void __launch_bounds__(32 * WARPS_PER_CTA, 3)
fogcn_main_kernel(const float* __restrict__ cnt,
                  const float* __restrict__ emb,
                  const int*   __restrict__ src,
                  float*       __restrict__ out,
                  int n_nodes) {
    extern __shared__ float sm[];
    int wid  = threadIdx.x >> 5;
    int lane = threadIdx.x & 31;
    float* s_cnt = sm + wid * (32 * CNT_STRIDE);

    int node = blockIdx.x * WARPS_PER_CTA + wid;
    if (node >= n_nodes) return;

    // lane r owns edge-row r of this node
    int e    = g_edge[node * DEG + lane];
    int srow = src[e];

    // --- cooperative coalesced cnt gather (16 lanes per 256B row),
    //     written into column-permuted layout (4-scalar scatter, 2-way bank) ---
    {
        int half  = lane >> 4;
        int u     = lane & 15;
        int dbase = (u >> 2) * 16 + (u & 3);
#pragma unroll
        for (int j = 0; j < 16; j++) {
            int row = 2 * j + half;
            int er  = __shfl_sync(0xffffffffu, e, row);
            float4 v = reinterpret_cast<const float4*>(cnt + (size_t)er * C_DIM)[u];
            float* d = s_cnt + row * CNT_STRIDE + dbase;
            d[0] = v.x; d[4] = v.y; d[8] = v.z; d[12] = v.w;
        }
    }
    __syncwarp();

    int gid = lane >> 2;     // row-group 0..7
    int tig = lane & 3;      // thread-in-group 0..3

    // emb base pointers for the 4 rows this lane reduces (rows j*8+gid)
    const float* embp[4];
#pragma unroll
    for (int j = 0; j < 4; j++) {
        int sr = __shfl_sync(0xffffffffu, srow, j * 8 + gid);
        embp[j] = emb + (size_t)sr * F_DIM + 2 * tig;
    }
    float* orow = out + (size_t)node * F_DIM;

#pragma unroll 1
    for (int cb = 0; cb < F_DIM; cb += 32) {
        float acc[2][4][4];
#pragma unroll
        for (int mt = 0; mt < 2; mt++)
#pragma unroll
            for (int t = 0; t < 4; t++)
#pragma unroll
                for (int i = 0; i < 4; i++) acc[mt][t][i] = 0.f;

#pragma unroll
        for (int d = 0; d < 4; d++) {
            // A fragments for k-steps 2d, 2d+1 (permuted layout -> LDS.128)
            float4 a4[2][2];   // [mt][row-half]
#pragma unroll
            for (int mt = 0; mt < 2; mt++) {
                a4[mt][0] = *reinterpret_cast<const float4*>(
                                s_cnt + (mt * 16 + gid) * CNT_STRIDE + d * 16 + 4 * tig);
                a4[mt][1] = *reinterpret_cast<const float4*>(
                                s_cnt + (mt * 16 + gid + 8) * CNT_STRIDE + d * 16 + 4 * tig);
            }
            // B fragments straight from global (L1-resident), LDG.128
            float4 b4[4];
#pragma unroll
            for (int t = 0; t < 4; t++)
                b4[t] = *reinterpret_cast<const float4*>(
                            g_wt + (cb + t * 8 + gid) * C_DIM + d * 16 + 4 * tig);

#pragma unroll
            for (int sub = 0; sub < 2; sub++) {
#pragma unroll
                for (int t = 0; t < 4; t++) {
                    uint32_t b0 = __float_as_uint(sub ? b4[t].z : b4[t].x);
                    uint32_t b1 = __float_as_uint(sub ? b4[t].w : b4[t].y);
#pragma unroll
                    for (int mt = 0; mt < 2; mt++) {
                        uint32_t a0 = __float_as_uint(sub ? a4[mt][0].z : a4[mt][0].x);
                        uint32_t a1 = __float_as_uint(sub ? a4[mt][1].z : a4[mt][1].x);
                        uint32_t a2 = __float_as_uint(sub ? a4[mt][0].w : a4[mt][0].y);
                        uint32_t a3 = __float_as_uint(sub ? a4[mt][1].w : a4[mt][1].y);
                        asm volatile(
                            "mma.sync.aligned.m16n8k8.row.col.f32.tf32.tf32.f32 "
                            "{%0,%1,%2,%3}, {%4,%5,%6,%7}, {%8,%9}, {%0,%1,%2,%3};"
                            : "+f"(acc[mt][t][0]), "+f"(acc[mt][t][1]),
                              "+f"(acc[mt][t][2]), "+f"(acc[mt][t][3])
                            : "r"(a0), "r"(a1), "r"(a2), "r"(a3),
                              "r"(b0), "r"(b1));
                    }
                }
            }
        }

        // --- epilogue in mma layout: scattered float2 emb loads + shfl reduce ---
#pragma unroll
        for (int t = 0; t < 4; t++) {
            float num0 = 0.f, num1 = 0.f, den0 = 0.f, den1 = 0.f;
#pragma unroll
            for (int mt = 0; mt < 2; mt++) {
                float2 lo = *reinterpret_cast<const float2*>(embp[2 * mt]     + cb + t * 8);
                float2 hi = *reinterpret_cast<const float2*>(embp[2 * mt + 1] + cb + t * 8);
                num0 = fmaf(acc[mt][t][0], lo.x, fmaf(acc[mt][t][2], hi.x, num0));
                num1 = fmaf(acc[mt][t][1], lo.y, fmaf(acc[mt][t][3], hi.y, num1));
                den0 += acc[mt][t][0] + acc[mt][t][2];
                den1 += acc[mt][t][1] + acc[mt][t][3];
            }
#pragma unroll
            for (int off = 4; off < 32; off <<= 1) {
                num0 += __shfl_xor_sync(0xffffffffu, num0, off);
                num1 += __shfl_xor_sync(0xffffffffu, num1, off);
                den0 += __shfl_xor_sync(0xffffffffu, den0, off);
                den1 += __shfl_xor_sync(0xffffffffu, den1, off);
            }
            if (gid == 0) {
                *reinterpret_cast<float2*>(orow + cb + t * 8 + 2 * tig) =
                    make_float2(__fdividef(num0, den0), __fdividef(num1, den1));
            }
        }
    }
}

// ---------------------------------------------------------------------------
extern "C" void kernel_launch(void* const* d_in, const int* in_sizes, int n_in,
                              void* d_out, int out_size) {
    const float* cnt = (const float*)d_in[0];
    const float* emb = (const float*)d_in[1];
    const float* imp = (const float*)d_in[2];
    const int*   src = (const int*)d_in[3];
    const int*   dst = (const int*)d_in[4];
    float*       out = (float*)d_out;

    int n_edges = in_sizes[3];
    int n_nodes = in_sizes[1] / F_DIM;
    if (n_edges > MAX_E) n_edges = MAX_E;
    if (n_nodes > MAX_N) n_nodes = MAX_N;

    // zero cursors + softmax weights in one launch
    int zero_blocks = (n_nodes + 255) / 256;
    prep1_kernel<<<zero_blocks + 1, 256>>>(imp, n_nodes);
    scatter_kernel<<<(n_edges + 255) / 256, 256>>>(dst, n_edges);

    int smem_bytes = WARPS_PER_CTA * 32 * CNT_STRIDE * (int)sizeof(float);  // 69632
    cudaFuncSetAttribute(fogcn_main_kernel,
                         cudaFuncAttributeMaxDynamicSharedMemorySize, smem_bytes);

    int nblocks = (n_nodes + WARPS_PER_CTA - 1) / WARPS_PER_CTA;
    fogcn_main_kernel<<<nblocks, 32 * WARPS_PER_CTA, smem_bytes>>>(cnt, emb, src, out, n_nodes);
}

// round 4
// speedup vs baseline: 1.9646x; 1.9646x over previous
#include <cuda_runtime.h>
#include <cuda_bf16.h>
#include <cstdint>

#define C_DIM 64
#define F_DIM 128
#define DEG 32
#define MAX_N 20000
#define MAX_E 640000
#define WARPS_PER_CTA 8
#define ROW_WORDS 40            // uint32 words per row in shared (32 payload + 8 pad)
#define WARP_SM_WORDS (32 * ROW_WORDS + 32)   // s_cnt/s_es + s_src
#define WT_WORDS (F_DIM * ROW_WORDS)

// Scratch (device globals: no allocations allowed in kernel_launch)
__device__ unsigned g_wt[F_DIM * 32];   // bf16x2-packed, pair-permuted W^T rows
__device__ int      g_cursor[MAX_N];
__device__ int      g_edge[MAX_E];      // per-node edge lists, DEG per node

// pack two floats (lo = even k, hi = odd k) to bf16x2
__device__ __forceinline__ unsigned pack_bf2(float lo, float hi) {
    unsigned r;
    asm("cvt.rn.bf16x2.f32 %0, %1, %2;" : "=r"(r) : "f"(hi), "f"(lo));
    return r;
}

// ---------------------------------------------------------------------------
// scatter (+ softmax in the last block)
// W^T row layout per feature f: 4 blocks of 16 k; within a block, k-pairs q
// are permuted to word position 2*(q&3)+(q>>2) so that thread tig's mma
// operand pair {k=2tig.., k=8+2tig..} is one contiguous uint2 (LDS.64).
// ---------------------------------------------------------------------------
__global__ void scatter_softmax_kernel(const int* __restrict__ dst, int n_edges,
                                       const float* __restrict__ imp) {
    if (blockIdx.x == gridDim.x - 1) {
        int f = threadIdx.x;
        if (f < F_DIM) {
            float v[C_DIM];
            float m = -3.0e38f;
#pragma unroll
            for (int c = 0; c < C_DIM; c++) { v[c] = imp[c * F_DIM + f]; m = fmaxf(m, v[c]); }
            float s = 0.f;
#pragma unroll
            for (int c = 0; c < C_DIM; c++) { v[c] = expf(v[c] - m); s += v[c]; }
            float inv = 1.0f / s;
#pragma unroll
            for (int c = 0; c < C_DIM; c++) v[c] *= inv;
#pragma unroll
            for (int b = 0; b < 4; b++)
#pragma unroll
                for (int q = 0; q < 8; q++) {
                    int c0 = b * 16 + 2 * q;
                    g_wt[f * 32 + b * 8 + 2 * (q & 3) + (q >> 2)] =
                        pack_bf2(v[c0], v[c0 + 1]);
                }
        }
        return;
    }
    int e = blockIdx.x * blockDim.x + threadIdx.x;
    if (e < n_edges) {
        int d = dst[e];
        int slot = atomicAdd(&g_cursor[d], 1);
        if (slot < DEG) g_edge[d * DEG + slot] = e;
    }
}

// ---------------------------------------------------------------------------
// Main fused kernel: one warp = one node; bf16 m16n8k16 mma.
// ---------------------------------------------------------------------------
__global__ void __launch_bounds__(32 * WARPS_PER_CTA, 2)
fogcn_main_kernel(const float* __restrict__ cnt,
                  const float* __restrict__ emb,
                  const int*   __restrict__ src,
                  float*       __restrict__ out,
                  int n_nodes) {
    extern __shared__ unsigned smu[];
    unsigned* s_wt = smu;                                   // [128][40] words
    int wid  = threadIdx.x >> 5;
    int lane = threadIdx.x & 31;
    int tid  = threadIdx.x;
    unsigned* s_cnt = smu + WT_WORDS + wid * WARP_SM_WORDS; // [32][40] words
    int*      s_src = (int*)(s_cnt + 32 * ROW_WORDS);       // [32]

    // CTA-cooperative: stage packed W^T rows into shared (stride 40 words)
    {
        int row = tid >> 1, half = tid & 1;   // 256 threads = 128 rows x 2 halves
        const uint4* g = reinterpret_cast<const uint4*>(g_wt + row * 32 + half * 16);
        uint4* d = reinterpret_cast<uint4*>(s_wt + row * ROW_WORDS + half * 16);
        d[0] = g[0]; d[1] = g[1]; d[2] = g[2]; d[3] = g[3];
    }
    __syncthreads();

    int node = blockIdx.x * WARPS_PER_CTA + wid;
    if (node >= n_nodes) return;

    int e    = g_edge[node * DEG + lane];
    int srow = src[e];
    s_src[lane] = srow;

    // --- cooperative coalesced cnt gather, bf16-packed + pair-permuted ---
    {
        int half = lane >> 4;
        int u    = lane & 15;
        // float4 covers cols 4u..4u+3 = pairs 2(u&3), 2(u&3)+1 of block u>>2;
        // permuted word offsets: base and base+2
        int boff = (u >> 2) * 8 + ((u & 1) * 4 + ((u >> 1) & 1));
#pragma unroll
        for (int j = 0; j < 16; j++) {
            int row = 2 * j + half;
            int er  = __shfl_sync(0xffffffffu, e, row);
            float4 v = reinterpret_cast<const float4*>(cnt + (size_t)er * C_DIM)[u];
            unsigned* drow = s_cnt + row * ROW_WORDS;
            drow[boff]     = pack_bf2(v.x, v.y);
            drow[boff + 2] = pack_bf2(v.z, v.w);
        }
    }
    __syncwarp();

    int gid = lane >> 2;     // row-group 0..7
    int tig = lane & 3;      // thread-in-group 0..3

    // --- hoist all A fragments (chunk-independent): 16 x LDS.64 = 32 regs ---
    uint2 af[4][2][2];       // [ks][mt][row-half]: .x = a(k 2tig..), .y = a(k 8+2tig..)
#pragma unroll
    for (int ks = 0; ks < 4; ks++)
#pragma unroll
        for (int mt = 0; mt < 2; mt++)
#pragma unroll
            for (int h = 0; h < 2; h++)
                af[ks][mt][h] = *reinterpret_cast<const uint2*>(
                    s_cnt + (mt * 16 + gid + h * 8) * ROW_WORDS + ks * 8 + 2 * tig);
    __syncwarp();            // s_cnt now dead -> reuse as s_es

    float* s_es = reinterpret_cast<float*>(s_cnt);   // [32][40] floats
    const float* embc = emb + lane;                  // lane owns chunk-column `lane`
    float* orow = out + (size_t)node * F_DIM;

#pragma unroll 1
    for (int cb = 0; cb < F_DIM; cb += 32) {
        float acc[2][4][4];
#pragma unroll
        for (int mt = 0; mt < 2; mt++)
#pragma unroll
            for (int t = 0; t < 4; t++)
#pragma unroll
                for (int i = 0; i < 4; i++) acc[mt][t][i] = 0.f;

#pragma unroll
        for (int ks = 0; ks < 4; ks++) {
            uint2 b2[4];
#pragma unroll
            for (int t = 0; t < 4; t++)
                b2[t] = *reinterpret_cast<const uint2*>(
                    s_wt + (cb + t * 8 + gid) * ROW_WORDS + ks * 8 + 2 * tig);
#pragma unroll
            for (int t = 0; t < 4; t++)
#pragma unroll
                for (int mt = 0; mt < 2; mt++)
                    asm volatile(
                        "mma.sync.aligned.m16n8k16.row.col.f32.bf16.bf16.f32 "
                        "{%0,%1,%2,%3}, {%4,%5,%6,%7}, {%8,%9}, {%0,%1,%2,%3};"
                        : "+f"(acc[mt][t][0]), "+f"(acc[mt][t][1]),
                          "+f"(acc[mt][t][2]), "+f"(acc[mt][t][3])
                        : "r"(af[ks][mt][0].x), "r"(af[ks][mt][1].x),
                          "r"(af[ks][mt][0].y), "r"(af[ks][mt][1].y),
                          "r"(b2[t].x), "r"(b2[t].y));
        }

        // --- write ES fragments to shared (stride 40, conflict-free) ---
        __syncwarp();
#pragma unroll
        for (int mt = 0; mt < 2; mt++)
#pragma unroll
            for (int t = 0; t < 4; t++) {
                int r = mt * 16 + gid;
                int c = t * 8 + tig * 2;
                *reinterpret_cast<float2*>(s_es + r * ROW_WORDS + c) =
                    make_float2(acc[mt][t][0], acc[mt][t][1]);
                *reinterpret_cast<float2*>(s_es + (r + 8) * ROW_WORDS + c) =
                    make_float2(acc[mt][t][2], acc[mt][t][3]);
            }
        __syncwarp();

        // --- reduction: lane = chunk-feature; coalesced emb loads ---
        float num = 0.f, den = 0.f;
#pragma unroll 8
        for (int r = 0; r < 32; r++) {
            float es = s_es[r * ROW_WORDS + lane];
            float ev = embc[(size_t)s_src[r] * F_DIM + cb];
            num = fmaf(es, ev, num);
            den += es;
        }
        orow[cb + lane] = __fdividef(num, den);
        __syncwarp();   // protect s_es before next chunk's stores
    }
}

// ---------------------------------------------------------------------------
extern "C" void kernel_launch(void* const* d_in, const int* in_sizes, int n_in,
                              void* d_out, int out_size) {
    const float* cnt = (const float*)d_in[0];
    const float* emb = (const float*)d_in[1];
    const float* imp = (const float*)d_in[2];
    const int*   src = (const int*)d_in[3];
    const int*   dst = (const int*)d_in[4];
    float*       out = (float*)d_out;

    int n_edges = in_sizes[3];
    int n_nodes = in_sizes[1] / F_DIM;
    if (n_edges > MAX_E) n_edges = MAX_E;
    if (n_nodes > MAX_N) n_nodes = MAX_N;

    // zero the cursors without a kernel launch
    void* cur_ptr = nullptr;
    cudaGetSymbolAddress(&cur_ptr, g_cursor);
    cudaMemsetAsync(cur_ptr, 0, (size_t)n_nodes * sizeof(int));

    // scatter + softmax fused (softmax in the extra last block)
    int sblocks = (n_edges + 255) / 256;
    scatter_softmax_kernel<<<sblocks + 1, 256>>>(dst, n_edges, imp);

    int smem_bytes = (WT_WORDS + WARPS_PER_CTA * WARP_SM_WORDS) * (int)sizeof(unsigned);
    cudaFuncSetAttribute(fogcn_main_kernel,
                         cudaFuncAttributeMaxDynamicSharedMemorySize, smem_bytes);

    int nblocks = (n_nodes + WARPS_PER_CTA - 1) / WARPS_PER_CTA;
    fogcn_main_kernel<<<nblocks, 32 * WARPS_PER_CTA, smem_bytes>>>(cnt, emb, src, out, n_nodes);
}